// round 1
// baseline (speedup 1.0000x reference)
#include <cuda_runtime.h>
#include <cuda_bf16.h>

#define NG 2048
#define HW 128
#define TANFOV 0.5f
#define NEARP 0.2f
#define AMIN (1.0f/255.0f)
#define LOG2E 1.4426950408889634f

// unsorted per-gaussian data
__device__ float4 g_ua[NG];   // px, py, ca2, cb2
__device__ float4 g_ub[NG];   // cc2, op, cullR2, (pad)
__device__ float4 g_uc[NG];   // r, g, b, (pad)
__device__ float  g_z[NG];
// depth-sorted
__device__ float4 g_sa[NG];
__device__ float4 g_sb[NG];
__device__ float4 g_sc[NG];

__global__ void preprocess_kernel(const float* __restrict__ means3D,
                                  const float* __restrict__ colors,
                                  const float* __restrict__ opacities,
                                  const float* __restrict__ cov3Ds,
                                  float* __restrict__ out_radii) {
    int i = blockIdx.x * blockDim.x + threadIdx.x;
    if (i >= NG) return;

    const float fx = HW / (2.0f * TANFOV);   // 128
    const float fy = fx;

    float x = means3D[3*i+0];
    float y = means3D[3*i+1];
    float z = means3D[3*i+2];
    float invz = 1.0f / z;

    float px = fx * x * invz + 0.5f * HW;
    float py = fy * y * invz + 0.5f * HW;

    const float lim = 1.3f * TANFOV;
    float txn = fminf(fmaxf(x * invz, -lim), lim) * z;
    float tyn = fminf(fmaxf(y * invz, -lim), lim) * z;

    float xx = cov3Ds[6*i+0], xy = cov3Ds[6*i+1], xz = cov3Ds[6*i+2];
    float yy = cov3Ds[6*i+3], yz = cov3Ds[6*i+4], zz = cov3Ds[6*i+5];

    float j00 = fx * invz;
    float j02 = -fx * txn * invz * invz;
    float j11 = fy * invz;
    float j12 = -fy * tyn * invz * invz;

    // M = J * S (rows 0 and 1)
    float M00 = j00*xx + j02*xz;
    float M01 = j00*xy + j02*yz;
    float M02 = j00*xz + j02*zz;
    float M10 = j11*xy + j12*xz;
    float M11 = j11*yy + j12*yz;
    float M12 = j11*yz + j12*zz;

    float a = M00*j00 + M02*j02 + 0.3f;     // cov2[0][0]+0.3
    float b = M01*j11 + M02*j12;            // cov2[0][1]
    float c = M11*j11 + M12*j12 + 0.3f;     // cov2[1][1]+0.3

    float det = a*c - b*b;
    float invdet = 1.0f / det;
    float conA = c * invdet;
    float conB = -b * invdet;
    float conC = a * invdet;

    float mid = 0.5f * (a + c);
    float lam1 = mid + sqrtf(fmaxf(0.1f, mid*mid - det));

    bool valid = (z > NEARP) && (det > 0.0f);
    float radii = valid ? ceilf(3.0f * sqrtf(lam1)) : 0.0f;
    out_radii[i] = radii;

    float op = opacities[i];
    // exact-safe cull radius^2: alpha <= op*exp(-0.5*d2/lam1) < AMIN  <=>  d2 > 2*lam1*ln(255*op)
    float cullR2;
    if (!valid) cullR2 = -1.0f;
    else {
        float t = op * 255.0f;
        cullR2 = (t <= 1.0f) ? -1.0f : 2.0f * lam1 * logf(t);
    }

    // fold -0.5*log2(e) into conic so blend uses exp2f directly
    float ca2 = -0.5f * LOG2E * conA;
    float cb2 = -LOG2E * conB;
    float cc2 = -0.5f * LOG2E * conC;

    g_ua[i] = make_float4(px, py, ca2, cb2);
    g_ub[i] = make_float4(cc2, op, cullR2, 0.0f);
    g_uc[i] = make_float4(colors[3*i+0], colors[3*i+1], colors[3*i+2], 0.0f);
    g_z[i]  = z;
}

// O(N^2) stable counting rank-sort + scatter into sorted arrays
__global__ void ranksort_kernel() {
    int i = blockIdx.x * blockDim.x + threadIdx.x;
    if (i >= NG) return;
    float zi = g_z[i];
    int rank = 0;
    #pragma unroll 8
    for (int j = 0; j < NG; j++) {
        float zj = g_z[j];
        rank += (zj < zi) || (zj == zi && j < i);
    }
    g_sa[rank] = g_ua[i];
    g_sb[rank] = g_ub[i];
    g_sc[rank] = g_uc[i];
}

// one 16x16 tile per block, 256 threads = 1 thread/pixel
__global__ void __launch_bounds__(256) blend_kernel(const float* __restrict__ bg,
                                                    float* __restrict__ out_img) {
    __shared__ float4 s_a[256];
    __shared__ float2 s_b[256];
    __shared__ float4 s_c[256];
    __shared__ int    s_cnt[8];

    int t = threadIdx.x;
    int tile = blockIdx.x;
    int tx0 = (tile & 7) * 16;
    int ty0 = (tile >> 3) * 16;
    float X = (float)(tx0 + (t & 15));
    float Y = (float)(ty0 + (t >> 4));
    float rx0 = (float)tx0, rx1 = (float)(tx0 + 15);
    float ry0 = (float)ty0, ry1 = (float)(ty0 + 15);

    float T = 1.0f, accr = 0.0f, accg = 0.0f, accb = 0.0f;
    int lane = t & 31, w = t >> 5;

    for (int base = 0; base < NG; base += 256) {
        int gi = base + t;
        float4 A = g_sa[gi];
        float4 B = g_sb[gi];
        // distance^2 from gaussian center to tile rect
        float ddx = fmaxf(0.0f, fmaxf(rx0 - A.x, A.x - rx1));
        float ddy = fmaxf(0.0f, fmaxf(ry0 - A.y, A.y - ry1));
        bool keep = (ddx*ddx + ddy*ddy) <= B.z;   // B.z < 0 => always skip

        unsigned bal = __ballot_sync(0xffffffffu, keep);
        if (lane == 0) s_cnt[w] = __popc(bal);
        __syncthreads();

        int off = 0, total = 0;
        #pragma unroll
        for (int k = 0; k < 8; k++) {
            int cn = s_cnt[k];
            off += (k < w) ? cn : 0;
            total += cn;
        }
        int pos = off + __popc(bal & ((1u << lane) - 1u));
        if (keep) {
            s_a[pos] = A;
            s_b[pos] = make_float2(B.x, B.y);
            s_c[pos] = g_sc[gi];
        }
        __syncthreads();

        for (int j = 0; j < total; j++) {
            float4 a = s_a[j];
            float2 bb = s_b[j];
            float4 cc = s_c[j];
            float dx = a.x - X;
            float dy = a.y - Y;
            float p2 = a.z*dx*dx + a.w*dx*dy + bb.x*dy*dy;  // = power * log2(e)
            float e = exp2f(p2);
            float alpha = fminf(bb.y * e, 0.99f);
            if (p2 > 0.0f || alpha < AMIN) alpha = 0.0f;
            float wgt = alpha * T;
            accr = fmaf(wgt, cc.x, accr);
            accg = fmaf(wgt, cc.y, accg);
            accb = fmaf(wgt, cc.z, accb);
            T = fmaf(-alpha, T, T);
        }
        __syncthreads();
    }

    int p = (ty0 + (t >> 4)) * HW + tx0 + (t & 15);
    out_img[p]                 = fmaf(T, bg[0], accr);
    out_img[HW*HW + p]         = fmaf(T, bg[1], accg);
    out_img[2*HW*HW + p]       = fmaf(T, bg[2], accb);
}

extern "C" void kernel_launch(void* const* d_in, const int* in_sizes, int n_in,
                              void* d_out, int out_size) {
    const float* means3D   = (const float*)d_in[0];
    const float* colors    = (const float*)d_in[1];
    const float* opacities = (const float*)d_in[2];
    const float* cov3Ds    = (const float*)d_in[3];
    const float* bg        = (const float*)d_in[4];
    float* out = (float*)d_out;
    float* out_img   = out;              // 3*128*128
    float* out_radii = out + 3*HW*HW;    // 2048

    preprocess_kernel<<<NG/256, 256>>>(means3D, colors, opacities, cov3Ds, out_radii);
    ranksort_kernel<<<NG/256, 256>>>();
    blend_kernel<<<64, 256>>>(bg, out_img);
}

// round 2
// speedup vs baseline: 2.7988x; 2.7988x over previous
#include <cuda_runtime.h>
#include <cuda_bf16.h>

#define NG 2048
#define HW 128
#define TANFOV 0.5f
#define NEARP 0.2f
#define AMIN (1.0f/255.0f)
#define LOG2E 1.4426950408889634f
#define TEPS 1e-7f

// depth-sorted per-gaussian data
__device__ float4 g_sa[NG];   // px, py, ca2, cb2
__device__ float4 g_sb[NG];   // cc2, op, cullR2, pad
__device__ float4 g_sc[NG];   // r, g, b, pad

__device__ __forceinline__ float fast_exp2(float x) {
    float r;
    asm("ex2.approx.f32 %0, %1;" : "=f"(r) : "f"(x));
    return r;
}

// Fused: rank-sort by z (warp-per-gaussian) + projection/conic preprocess,
// scattered directly into depth-sorted arrays. 64 CTAs x 1024 threads.
__global__ void __launch_bounds__(1024) prep_sort_kernel(
        const float* __restrict__ means3D,
        const float* __restrict__ colors,
        const float* __restrict__ opacities,
        const float* __restrict__ cov3Ds,
        float* __restrict__ out_radii) {
    __shared__ float s_z[NG];
    int t = threadIdx.x;

    // stage all z into smem
    for (int j = t; j < NG; j += 1024) s_z[j] = means3D[3*j + 2];
    __syncthreads();

    int w = t >> 5, lane = t & 31;
    int i = blockIdx.x * 32 + w;          // gaussian handled by this warp
    float zi = s_z[i];

    // stable rank of z_i (counts of smaller, ties broken by index)
    int cnt = 0;
    #pragma unroll 4
    for (int j = lane; j < NG; j += 32) {
        float zj = s_z[j];
        cnt += (zj < zi) || (zj == zi && j < i);
    }
    int rank = __reduce_add_sync(0xffffffffu, cnt);

    // ---- preprocess (all lanes redundantly; lane 0 writes) ----
    const float fx = HW / (2.0f * TANFOV);
    const float fy = fx;

    float x = means3D[3*i + 0];
    float y = means3D[3*i + 1];
    float z = zi;
    float invz = 1.0f / z;

    float px = fx * x * invz + 0.5f * HW;
    float py = fy * y * invz + 0.5f * HW;

    const float lim = 1.3f * TANFOV;
    float txn = fminf(fmaxf(x * invz, -lim), lim) * z;
    float tyn = fminf(fmaxf(y * invz, -lim), lim) * z;

    float xx = cov3Ds[6*i+0], xy = cov3Ds[6*i+1], xz = cov3Ds[6*i+2];
    float yy = cov3Ds[6*i+3], yz = cov3Ds[6*i+4], zz = cov3Ds[6*i+5];

    float j00 = fx * invz;
    float j02 = -fx * txn * invz * invz;
    float j11 = fy * invz;
    float j12 = -fy * tyn * invz * invz;

    float M00 = j00*xx + j02*xz;
    float M01 = j00*xy + j02*yz;
    float M02 = j00*xz + j02*zz;
    float M11 = j11*yy + j12*yz;
    float M12 = j11*yz + j12*zz;

    float a = M00*j00 + M02*j02 + 0.3f;
    float b = M01*j11 + M02*j12;
    float c = M11*j11 + M12*j12 + 0.3f;

    float det = a*c - b*b;
    float invdet = 1.0f / det;
    float conA = c * invdet;
    float conB = -b * invdet;
    float conC = a * invdet;

    float mid = 0.5f * (a + c);
    float lam1 = mid + sqrtf(fmaxf(0.1f, mid*mid - det));

    bool valid = (z > NEARP) && (det > 0.0f);
    float radii = valid ? ceilf(3.0f * sqrtf(lam1)) : 0.0f;

    float op = opacities[i];
    // exact cull radius^2: alpha < AMIN guaranteed when d2 > 2*lam1*ln(255*op)
    float cullR2;
    if (!valid) cullR2 = -1.0f;
    else {
        float tt = op * 255.0f;
        cullR2 = (tt <= 1.0f) ? -1.0f : 2.0f * lam1 * logf(tt);
    }

    float ca2 = -0.5f * LOG2E * conA;
    float cb2 = -LOG2E * conB;
    float cc2 = -0.5f * LOG2E * conC;

    if (lane == 0) {
        out_radii[i] = radii;
        g_sa[rank] = make_float4(px, py, ca2, cb2);
        g_sb[rank] = make_float4(cc2, op, cullR2, 0.0f);
        g_sc[rank] = make_float4(colors[3*i+0], colors[3*i+1], colors[3*i+2], 0.0f);
    }
}

// one 16x16 tile per block, 256 threads = 1 thread/pixel
__global__ void __launch_bounds__(256) blend_kernel(const float* __restrict__ bg,
                                                    float* __restrict__ out_img) {
    __shared__ float4 s_a[256];
    __shared__ float2 s_b[256];
    __shared__ float4 s_c[256];
    __shared__ int    s_cnt[8];

    int t = threadIdx.x;
    int tile = blockIdx.x;
    int tx0 = (tile & 7) * 16;
    int ty0 = (tile >> 3) * 16;
    float X = (float)(tx0 + (t & 15));
    float Y = (float)(ty0 + (t >> 4));
    float rx0 = (float)tx0, rx1 = (float)(tx0 + 15);
    float ry0 = (float)ty0, ry1 = (float)(ty0 + 15);

    float T = 1.0f, accr = 0.0f, accg = 0.0f, accb = 0.0f;
    int lane = t & 31, w = t >> 5;

    for (int base = 0; base < NG; base += 256) {
        int gi = base + t;
        float4 A = g_sa[gi];
        float4 B = g_sb[gi];
        // distance^2 from gaussian center to tile rect vs exact cull radius
        float ddx = fmaxf(0.0f, fmaxf(rx0 - A.x, A.x - rx1));
        float ddy = fmaxf(0.0f, fmaxf(ry0 - A.y, A.y - ry1));
        bool keep = (ddx*ddx + ddy*ddy) <= B.z;   // B.z < 0 => skip

        unsigned bal = __ballot_sync(0xffffffffu, keep);
        if (lane == 0) s_cnt[w] = __popc(bal);
        __syncthreads();

        int off = 0, total = 0;
        #pragma unroll
        for (int k = 0; k < 8; k++) {
            int cn = s_cnt[k];
            off += (k < w) ? cn : 0;
            total += cn;
        }
        int pos = off + __popc(bal & ((1u << lane) - 1u));
        if (keep) {
            s_a[pos] = A;
            s_b[pos] = make_float2(B.x, B.y);
            s_c[pos] = g_sc[gi];
        }
        __syncthreads();

        for (int j = 0; j < total; j++) {
            // warp-level early termination: all further weights < TEPS
            if (__ballot_sync(0xffffffffu, T >= TEPS) == 0u) break;
            float4 a = s_a[j];
            float2 bb = s_b[j];
            float4 cc = s_c[j];
            float dx = a.x - X;
            float dy = a.y - Y;
            float p2 = a.z*dx*dx + a.w*dx*dy + bb.x*dy*dy;  // power * log2(e)
            float e = fast_exp2(p2);
            float alpha = fminf(bb.y * e, 0.99f);
            if (p2 > 0.0f || alpha < AMIN) alpha = 0.0f;
            float wgt = alpha * T;
            accr = fmaf(wgt, cc.x, accr);
            accg = fmaf(wgt, cc.y, accg);
            accb = fmaf(wgt, cc.z, accb);
            T = fmaf(-alpha, T, T);
        }

        // CTA-level early termination (also a barrier for the smem reuse)
        int nalive = __syncthreads_count(T >= TEPS);
        if (nalive == 0) break;
    }

    int p = (ty0 + (t >> 4)) * HW + tx0 + (t & 15);
    out_img[p]           = fmaf(T, bg[0], accr);
    out_img[HW*HW + p]   = fmaf(T, bg[1], accg);
    out_img[2*HW*HW + p] = fmaf(T, bg[2], accb);
}

extern "C" void kernel_launch(void* const* d_in, const int* in_sizes, int n_in,
                              void* d_out, int out_size) {
    const float* means3D   = (const float*)d_in[0];
    const float* colors    = (const float*)d_in[1];
    const float* opacities = (const float*)d_in[2];
    const float* cov3Ds    = (const float*)d_in[3];
    const float* bg        = (const float*)d_in[4];
    float* out = (float*)d_out;
    float* out_img   = out;              // 3*128*128
    float* out_radii = out + 3*HW*HW;    // 2048

    prep_sort_kernel<<<NG/32, 1024>>>(means3D, colors, opacities, cov3Ds, out_radii);
    blend_kernel<<<64, 256>>>(bg, out_img);
}

// round 3
// speedup vs baseline: 5.8286x; 2.0825x over previous
#include <cuda_runtime.h>
#include <cuda_bf16.h>

#define NG 2048
#define HW 128
#define TANFOV 0.5f
#define NEARP 0.2f
#define AMIN (1.0f/255.0f)
#define LOG2E 1.4426950408889634f
#define TEPS 1e-7f
#define CHUNKS 8
#define CHSZ (NG/CHUNKS)      // 256 gaussians per depth chunk

// depth-sorted per-gaussian data
__device__ float4 g_sa[NG];   // px, py, ca2, cb2
__device__ float4 g_sb[NG];   // cc2, op, cullR2, pad
__device__ float4 g_sc[NG];   // r, g, b, pad
// per-chunk partial (r,g,b,T) per pixel
__device__ float4 g_part[CHUNKS][HW*HW];

__device__ __forceinline__ float fast_exp2(float x) {
    float r;
    asm("ex2.approx.f32 %0, %1;" : "=f"(r) : "f"(x));
    return r;
}

// Fused: rank-sort by z (warp-per-gaussian) + projection/conic preprocess,
// scattered directly into depth-sorted arrays. 64 CTAs x 1024 threads.
__global__ void __launch_bounds__(1024) prep_sort_kernel(
        const float* __restrict__ means3D,
        const float* __restrict__ colors,
        const float* __restrict__ opacities,
        const float* __restrict__ cov3Ds,
        float* __restrict__ out_radii) {
    __shared__ float s_z[NG];
    int t = threadIdx.x;

    for (int j = t; j < NG; j += 1024) s_z[j] = means3D[3*j + 2];
    __syncthreads();

    int w = t >> 5, lane = t & 31;
    int i = blockIdx.x * 32 + w;
    float zi = s_z[i];

    int cnt = 0;
    #pragma unroll 4
    for (int j = lane; j < NG; j += 32) {
        float zj = s_z[j];
        cnt += (zj < zi) || (zj == zi && j < i);
    }
    int rank = __reduce_add_sync(0xffffffffu, cnt);

    const float fx = HW / (2.0f * TANFOV);
    const float fy = fx;

    float x = means3D[3*i + 0];
    float y = means3D[3*i + 1];
    float z = zi;
    float invz = 1.0f / z;

    float px = fx * x * invz + 0.5f * HW;
    float py = fy * y * invz + 0.5f * HW;

    const float lim = 1.3f * TANFOV;
    float txn = fminf(fmaxf(x * invz, -lim), lim) * z;
    float tyn = fminf(fmaxf(y * invz, -lim), lim) * z;

    float xx = cov3Ds[6*i+0], xy = cov3Ds[6*i+1], xz = cov3Ds[6*i+2];
    float yy = cov3Ds[6*i+3], yz = cov3Ds[6*i+4], zz = cov3Ds[6*i+5];

    float j00 = fx * invz;
    float j02 = -fx * txn * invz * invz;
    float j11 = fy * invz;
    float j12 = -fy * tyn * invz * invz;

    float M00 = j00*xx + j02*xz;
    float M01 = j00*xy + j02*yz;
    float M02 = j00*xz + j02*zz;
    float M11 = j11*yy + j12*yz;
    float M12 = j11*yz + j12*zz;

    float a = M00*j00 + M02*j02 + 0.3f;
    float b = M01*j11 + M02*j12;
    float c = M11*j11 + M12*j12 + 0.3f;

    float det = a*c - b*b;
    float invdet = 1.0f / det;
    float conA = c * invdet;
    float conB = -b * invdet;
    float conC = a * invdet;

    float mid = 0.5f * (a + c);
    float lam1 = mid + sqrtf(fmaxf(0.1f, mid*mid - det));

    bool valid = (z > NEARP) && (det > 0.0f);
    float radii = valid ? ceilf(3.0f * sqrtf(lam1)) : 0.0f;

    float op = opacities[i];
    float cullR2;
    if (!valid) cullR2 = -1.0f;
    else {
        float tt = op * 255.0f;
        cullR2 = (tt <= 1.0f) ? -1.0f : 2.0f * lam1 * logf(tt);
    }

    float ca2 = -0.5f * LOG2E * conA;
    float cb2 = -LOG2E * conB;
    float cc2 = -0.5f * LOG2E * conC;

    if (lane == 0) {
        out_radii[i] = radii;
        g_sa[rank] = make_float4(px, py, ca2, cb2);
        g_sb[rank] = make_float4(cc2, op, cullR2, 0.0f);
        g_sc[rank] = make_float4(colors[3*i+0], colors[3*i+1], colors[3*i+2], 0.0f);
    }
}

// grid (64 tiles, 8 depth chunks); one 16x16 tile, one 256-gaussian chunk per CTA.
__global__ void __launch_bounds__(256) blend_kernel() {
    __shared__ float4 s_a[256];
    __shared__ float2 s_b[256];
    __shared__ float4 s_c[256];
    __shared__ int    s_cnt[8];

    int t = threadIdx.x;
    int tile = blockIdx.x;
    int chunk = blockIdx.y;
    int tx0 = (tile & 7) * 16;
    int ty0 = (tile >> 3) * 16;
    float X = (float)(tx0 + (t & 15));
    float Y = (float)(ty0 + (t >> 4));
    float rx0 = (float)tx0, rx1 = (float)(tx0 + 15);
    float ry0 = (float)ty0, ry1 = (float)(ty0 + 15);

    int lane = t & 31, w = t >> 5;

    int gi = chunk * CHSZ + t;
    float4 A = g_sa[gi];
    float4 B = g_sb[gi];
    float ddx = fmaxf(0.0f, fmaxf(rx0 - A.x, A.x - rx1));
    float ddy = fmaxf(0.0f, fmaxf(ry0 - A.y, A.y - ry1));
    bool keep = (ddx*ddx + ddy*ddy) <= B.z;   // B.z < 0 => skip

    unsigned bal = __ballot_sync(0xffffffffu, keep);
    if (lane == 0) s_cnt[w] = __popc(bal);
    __syncthreads();

    int off = 0, total = 0;
    #pragma unroll
    for (int k = 0; k < 8; k++) {
        int cn = s_cnt[k];
        off += (k < w) ? cn : 0;
        total += cn;
    }
    int pos = off + __popc(bal & ((1u << lane) - 1u));
    if (keep) {
        s_a[pos] = A;
        s_b[pos] = make_float2(B.x, B.y);
        s_c[pos] = g_sc[gi];
    }
    __syncthreads();

    float T = 1.0f, accr = 0.0f, accg = 0.0f, accb = 0.0f;
    for (int j = 0; j < total; j++) {
        if (__ballot_sync(0xffffffffu, T >= TEPS) == 0u) break;
        float4 a = s_a[j];
        float2 bb = s_b[j];
        float4 cc = s_c[j];
        float dx = a.x - X;
        float dy = a.y - Y;
        float p2 = a.z*dx*dx + a.w*dx*dy + bb.x*dy*dy;  // power * log2(e)
        float e = fast_exp2(p2);
        float alpha = fminf(bb.y * e, 0.99f);
        if (p2 > 0.0f || alpha < AMIN) alpha = 0.0f;
        float wgt = alpha * T;
        accr = fmaf(wgt, cc.x, accr);
        accg = fmaf(wgt, cc.y, accg);
        accb = fmaf(wgt, cc.z, accb);
        T = fmaf(-alpha, T, T);
    }

    int p = (ty0 + (t >> 4)) * HW + tx0 + (t & 15);
    g_part[chunk][p] = make_float4(accr, accg, accb, T);
}

// fold the 8 depth-chunk partials front-to-back per pixel
__global__ void __launch_bounds__(256) combine_kernel(const float* __restrict__ bg,
                                                      float* __restrict__ out_img) {
    int p = blockIdx.x * 256 + threadIdx.x;
    float T = 1.0f, r = 0.0f, g = 0.0f, b = 0.0f;
    #pragma unroll
    for (int k = 0; k < CHUNKS; k++) {
        float4 c = g_part[k][p];
        r = fmaf(T, c.x, r);
        g = fmaf(T, c.y, g);
        b = fmaf(T, c.z, b);
        T *= c.w;
    }
    out_img[p]           = fmaf(T, bg[0], r);
    out_img[HW*HW + p]   = fmaf(T, bg[1], g);
    out_img[2*HW*HW + p] = fmaf(T, bg[2], b);
}

extern "C" void kernel_launch(void* const* d_in, const int* in_sizes, int n_in,
                              void* d_out, int out_size) {
    const float* means3D   = (const float*)d_in[0];
    const float* colors    = (const float*)d_in[1];
    const float* opacities = (const float*)d_in[2];
    const float* cov3Ds    = (const float*)d_in[3];
    const float* bg        = (const float*)d_in[4];
    float* out = (float*)d_out;
    float* out_img   = out;              // 3*128*128
    float* out_radii = out + 3*HW*HW;    // 2048

    prep_sort_kernel<<<NG/32, 1024>>>(means3D, colors, opacities, cov3Ds, out_radii);
    blend_kernel<<<dim3(64, CHUNKS), 256>>>();
    combine_kernel<<<HW*HW/256, 256>>>(bg, out_img);
}